// round 13
// baseline (speedup 1.0000x reference)
#include <cuda_runtime.h>

#define NXC 512
#define NYC 512
#define PHW 3
#define PP 6                   // patch size
#define BB 128
#define SS 1024
#define BH 16                  // band height (rows)
#define BANDS_PER_IMG (NXC / BH)      // 32
#define NBANDS (BB * BANDS_PER_IMG)   // 4096
#define NT 512                 // threads per block (16 warps)
#define CAP 96                 // max sources per band (mean ~42)
#define NBKT 16                // 32-col stripes
#define BCAP 24                // per-bucket capacity (mean ~3)

__device__ __forceinline__ float inv_alpha() { return 1.0f / (1.41421356237309515f * 0.92f); }

__global__ __launch_bounds__(NT, 2) void render_kernel(const float* __restrict__ z,
                                                       float* __restrict__ out) {
    __shared__ float  band[BH * NYC];                 // 32 KB, exclusive per-warp col stripes
    __shared__ float2 s_src[CAP];
    __shared__ float  s_lx[CAP * PP];
    __shared__ float  s_ly[CAP * PP];
    __shared__ int    s_px[CAP];
    __shared__ int    s_py[CAP];
    __shared__ int    s_bcnt[NBKT];
    __shared__ unsigned char s_blist[NBKT][BCAP];
    __shared__ int    s_n;

    int blk = blockIdx.x;
    int b   = blk >> 5;                               // image
    int r0  = (blk & (BANDS_PER_IMG - 1)) << 4;       // first global row of band
    int tid = threadIdx.x;
    int wid = tid >> 5;
    int lane = tid & 31;

    if (tid == 0) s_n = 0;
    if (tid < NBKT) s_bcnt[tid] = 0;

    // zero band: 2048 float4 over 512 threads
    float4* bz = (float4*)band;
#pragma unroll
    for (int k = 0; k < BH * NYC / 4 / NT; ++k)
        bz[k * NT + tid] = make_float4(0.f, 0.f, 0.f, 0.f);
    __syncthreads();

    // 1) scan this image's sources (coalesced), keep those intersecting the band
    {
        const float* zx = z + (size_t)b * 2 * SS;
#pragma unroll
        for (int k = 0; k < SS / NT; ++k) {
            int s = tid + k * NT;
            float x0 = __ldg(&zx[s]);
            float y0 = __ldg(&zx[SS + s]);
            int patchx = __float2int_rn(x0) - PHW;
            int patchy = __float2int_rn(y0) - PHW;
            bool valid = (patchx >= 0) & (patchx < NXC - PP) &
                         (patchy >= 0) & (patchy < NYC - PP);
            bool hit = valid & (patchx >= r0 - (PP - 1)) & (patchx < r0 + BH);
            if (hit) {
                int pos = atomicAdd(&s_n, 1);
                if (pos < CAP) s_src[pos] = make_float2(x0, y0);
            }
        }
    }
    __syncthreads();

    int n = s_n;
    if (n > CAP) n = CAP;

    // 2) per-source-per-axis setup: 2 threads per source; y-thread also buckets by stripe
    if (tid < 2 * n) {
        int sid = tid >> 1;
        int ax  = tid & 1;
        float2 xy = s_src[sid];
        float u0 = ax ? xy.y : xy.x;
        int pu = __float2int_rn(u0) - PHW;
        float up = u0 - (float)pu;
        const float ia = inv_alpha();

        float e[PP + 1];
#pragma unroll
        for (int k = 0; k <= PP; k++)
            e[k] = erff(((float)k - 0.5f - up) * ia);

        if (ax == 0) {
            s_px[sid] = pu;
#pragma unroll
            for (int k = 0; k < PP; k++)
                s_lx[sid * PP + k] = 500.0f * (e[k + 1] - e[k]);  // i0*0.5 folded
        } else {
            s_py[sid] = pu;
#pragma unroll
            for (int k = 0; k < PP; k++)
                s_ly[sid * PP + k] = 0.5f * (e[k + 1] - e[k]);
            int b0 = pu >> 5;
            int b1 = (pu + PP - 1) >> 5;
            for (int bd = b0; bd <= b1; ++bd) {
                int pos = atomicAdd(&s_bcnt[bd], 1);
                if (pos < BCAP) s_blist[bd][pos] = (unsigned char)sid;
            }
        }
    }
    __syncthreads();

    // 3) gather: warp w exclusively owns cols [32w, 32w+31] of the band -> no atomics.
    //    Only the 6 patch rows are visited per source.
    int col = (wid << 5) + lane;
    int cnt = s_bcnt[wid];
    if (cnt > BCAP) cnt = BCAP;
    for (int k = 0; k < cnt; ++k) {
        int s  = s_blist[wid][k];
        int rl = s_px[s] - r0;                        // warp-uniform, in [-5, 15]
        int dc = col - s_py[s];
        float ly = ((unsigned)dc < (unsigned)PP) ? s_ly[s * PP + dc] : 0.f;
#pragma unroll
        for (int i = 0; i < PP; ++i) {
            int r = rl + i;                           // warp-uniform predicate
            if ((unsigned)r < (unsigned)BH)
                band[r * NYC + col] += s_lx[s * PP + i] * ly;   // LDS+FFMA+STS, conflict-free
        }
    }
    __syncthreads();

    // 4) store: band stride == NYC, so flat coalesced float4 copy
    float4* dst = (float4*)(out + (size_t)b * NXC * NYC + (size_t)r0 * NYC);
#pragma unroll
    for (int k = 0; k < BH * NYC / 4 / NT; ++k) {
        int f = k * NT + tid;
        dst[f] = bz[f];
    }
}

extern "C" void kernel_launch(void* const* d_in, const int* in_sizes, int n_in,
                              void* d_out, int out_size) {
    const float* z = (const float*)d_in[0];
    float* out = (float*)d_out;
    render_kernel<<<NBANDS, NT>>>(z, out);
}

// round 14
// speedup vs baseline: 1.4711x; 1.4711x over previous
#include <cuda_runtime.h>

#define NXC 512
#define NYC 512
#define PHW 3
#define PP 6                   // patch size
#define BB 128
#define SS 1024
#define BH 32                  // band height (rows)
#define BANDS_PER_IMG (NXC / BH)      // 16
#define NBANDS (BB * BANDS_PER_IMG)   // 2048
#define NT 512                 // threads per block
#define CAP 192                // max sources per band (mean ~75)
#define NBKT 16                // 32-col stripes
#define BCAP 32                // per-bucket capacity (mean ~5.5)

__device__ __forceinline__ float inv_alpha() { return 1.0f / (1.41421356237309515f * 0.92f); }

// statically-indexed 6-row accumulate; RL = warp-uniform local patch-origin row
template<int RL>
__device__ __forceinline__ void acc6(float* acc, const float* s_lx, int sb, float ly) {
#pragma unroll
    for (int i = 0; i < PP; ++i) {
        const int r = RL + i;                 // compile-time
        if (r >= 0 && r < BH)
            acc[r] += s_lx[sb + i] * ly;      // static register index
    }
}

__global__ __launch_bounds__(NT, 2) void render_kernel(const float* __restrict__ z,
                                                       float* __restrict__ out) {
    __shared__ float2 s_src[CAP];
    __shared__ float  s_lx[CAP * PP];
    __shared__ float  s_ly[CAP * PP];
    __shared__ int    s_px[CAP];
    __shared__ int    s_py[CAP];
    __shared__ int    s_bcnt[NBKT];
    __shared__ unsigned char s_blist[NBKT][BCAP];
    __shared__ int    s_n;

    int blk = blockIdx.x;
    int b   = blk >> 4;                               // image
    int r0  = (blk & (BANDS_PER_IMG - 1)) << 5;       // first global row of band
    int tid = threadIdx.x;
    int wid = tid >> 5;
    int lane = tid & 31;

    if (tid == 0) s_n = 0;
    if (tid < NBKT) s_bcnt[tid] = 0;
    __syncthreads();

    // 1) scan this image's sources (coalesced), keep those intersecting the band
    {
        const float* zx = z + (size_t)b * 2 * SS;
#pragma unroll
        for (int k = 0; k < SS / NT; ++k) {
            int s = tid + k * NT;
            float x0 = __ldg(&zx[s]);
            float y0 = __ldg(&zx[SS + s]);
            int patchx = __float2int_rn(x0) - PHW;
            int patchy = __float2int_rn(y0) - PHW;
            bool valid = (patchx >= 0) & (patchx < NXC - PP) &
                         (patchy >= 0) & (patchy < NYC - PP);
            bool hit = valid & (patchx >= r0 - (PP - 1)) & (patchx < r0 + BH);
            if (hit) {
                int pos = atomicAdd(&s_n, 1);
                if (pos < CAP) s_src[pos] = make_float2(x0, y0);
            }
        }
    }
    __syncthreads();

    int n = s_n;
    if (n > CAP) n = CAP;

    // 2) per-source-per-axis setup: 2 threads per source; y-thread also buckets by stripe
    if (tid < 2 * n) {
        int sid = tid >> 1;
        int ax  = tid & 1;
        float2 xy = s_src[sid];
        float u0 = ax ? xy.y : xy.x;
        int pu = __float2int_rn(u0) - PHW;
        float up = u0 - (float)pu;
        const float ia = inv_alpha();

        float e[PP + 1];
#pragma unroll
        for (int k = 0; k <= PP; k++)
            e[k] = erff(((float)k - 0.5f - up) * ia);

        if (ax == 0) {
            s_px[sid] = pu;
#pragma unroll
            for (int k = 0; k < PP; k++)
                s_lx[sid * PP + k] = 500.0f * (e[k + 1] - e[k]);  // i0*0.5 folded
        } else {
            s_py[sid] = pu;
#pragma unroll
            for (int k = 0; k < PP; k++)
                s_ly[sid * PP + k] = 0.5f * (e[k + 1] - e[k]);
            int b0 = pu >> 5;
            int b1 = (pu + PP - 1) >> 5;
            for (int bd = b0; bd <= b1; ++bd) {
                int pos = atomicAdd(&s_bcnt[bd], 1);
                if (pos < BCAP) s_blist[bd][pos] = (unsigned char)sid;
            }
        }
    }
    __syncthreads();

    // 3) gather: warp w owns cols [32w, 32w+31]; lane owns 1 col, 32 rows in regs.
    //    rl is warp-uniform -> static-index dispatch touches only the 6 patch rows.
    int col = (wid << 5) + lane;
    float acc[BH];
#pragma unroll
    for (int r = 0; r < BH; ++r) acc[r] = 0.f;

    int cnt = s_bcnt[wid];
    if (cnt > BCAP) cnt = BCAP;
    for (int k = 0; k < cnt; ++k) {
        int s  = s_blist[wid][k];
        int rl = s_px[s] - r0;                        // warp-uniform, in [-5, 31]
        int dc = col - s_py[s];
        float ly = ((unsigned)dc < (unsigned)PP) ? s_ly[s * PP + dc] : 0.f;
        int sb = s * PP;
        switch (rl) {
#define ACC_CASE(RL) case RL: acc6<RL>(acc, s_lx, sb, ly); break;
            ACC_CASE(-5) ACC_CASE(-4) ACC_CASE(-3) ACC_CASE(-2) ACC_CASE(-1)
            ACC_CASE(0)  ACC_CASE(1)  ACC_CASE(2)  ACC_CASE(3)  ACC_CASE(4)
            ACC_CASE(5)  ACC_CASE(6)  ACC_CASE(7)  ACC_CASE(8)  ACC_CASE(9)
            ACC_CASE(10) ACC_CASE(11) ACC_CASE(12) ACC_CASE(13) ACC_CASE(14)
            ACC_CASE(15) ACC_CASE(16) ACC_CASE(17) ACC_CASE(18) ACC_CASE(19)
            ACC_CASE(20) ACC_CASE(21) ACC_CASE(22) ACC_CASE(23) ACC_CASE(24)
            ACC_CASE(25) ACC_CASE(26) ACC_CASE(27) ACC_CASE(28) ACC_CASE(29)
            ACC_CASE(30) ACC_CASE(31)
#undef ACC_CASE
            default: break;
        }
    }

    // 4) store: coalesced (128 B per warp-row)
    float* base = out + (size_t)b * NXC * NYC + (size_t)r0 * NYC + col;
#pragma unroll
    for (int r = 0; r < BH; ++r)
        base[r * NYC] = acc[r];
}

extern "C" void kernel_launch(void* const* d_in, const int* in_sizes, int n_in,
                              void* d_out, int out_size) {
    const float* z = (const float*)d_in[0];
    float* out = (float*)d_out;
    render_kernel<<<NBANDS, NT>>>(z, out);
}